// round 1
// baseline (speedup 1.0000x reference)
#include <cuda_runtime.h>

#define B_  16
#define CL_ 512
#define N_  3136
#define NV_ (N_ / 4)   // 784 float4 per row

// Scratch (allocation-free rule: __device__ globals)
__device__ float d_g[B_ * N_];     // g[b,n]
__device__ float d_tsum[B_];       // sum over n of t[b,n]

__global__ void init_kernel() {
    if (threadIdx.x < B_) d_tsum[threadIdx.x] = 0.0f;
}

// Pass 1: t[b,n] = sum_c x[b,c,n]*theta_w[c]; g[b,n] = sum_c x[b,c,n]*g_w[c]
// Store g, block-reduce t and atomicAdd into d_tsum[b].
__global__ __launch_bounds__(256) void reduce_kernel(
    const float* __restrict__ x,
    const float* __restrict__ theta_w,
    const float* __restrict__ g_w)
{
    __shared__ float s_tw[CL_];
    __shared__ float s_gw[CL_];
    __shared__ float s_red[256];

    const int b = blockIdx.y;
    const int n = blockIdx.x * blockDim.x + threadIdx.x;

    for (int c = threadIdx.x; c < CL_; c += blockDim.x) {
        s_tw[c] = theta_w[c];
        s_gw[c] = g_w[c];
    }
    __syncthreads();

    float t = 0.0f, g = 0.0f;
    if (n < N_) {
        const float* xp = x + (size_t)b * CL_ * N_ + n;
        #pragma unroll 8
        for (int c = 0; c < CL_; c++) {
            float v = __ldg(&xp[(size_t)c * N_]);
            t = fmaf(v, s_tw[c], t);
            g = fmaf(v, s_gw[c], g);
        }
        d_g[b * N_ + n] = g;
    }

    // block reduction of t
    s_red[threadIdx.x] = t;
    __syncthreads();
    #pragma unroll
    for (int off = 128; off > 0; off >>= 1) {
        if (threadIdx.x < off) s_red[threadIdx.x] += s_red[threadIdx.x + off];
        __syncthreads();
    }
    if (threadIdx.x == 0) atomicAdd(&d_tsum[b], s_red[0]);
}

// Pass 2: out[b,c,n] = x + g[b,n] * (tsum[b]/N) * h_w[c] + h_b[c]
__global__ __launch_bounds__(256) void out_kernel(
    const float* __restrict__ x,
    const float* __restrict__ h_w,
    const float* __restrict__ h_b,
    float* __restrict__ out)
{
    const int v = blockIdx.x * blockDim.x + threadIdx.x;   // float4 index
    const int n4  = v % NV_;
    const int row = v / NV_;          // row = b*CL + c
    const int c   = row % CL_;
    const int b   = row / CL_;

    const float mt  = d_tsum[b] * (1.0f / (float)N_);
    const float hwc = h_w[c] * mt;
    const float hbc = h_b[c];

    const float4 g4 = *reinterpret_cast<const float4*>(&d_g[b * N_ + n4 * 4]);
    const float4 x4 = reinterpret_cast<const float4*>(x)[v];

    float4 o;
    o.x = fmaf(g4.x, hwc, x4.x) + hbc;
    o.y = fmaf(g4.y, hwc, x4.y) + hbc;
    o.z = fmaf(g4.z, hwc, x4.z) + hbc;
    o.w = fmaf(g4.w, hwc, x4.w) + hbc;

    reinterpret_cast<float4*>(out)[v] = o;
}

extern "C" void kernel_launch(void* const* d_in, const int* in_sizes, int n_in,
                              void* d_out, int out_size)
{
    const float* x       = (const float*)d_in[0];
    const float* theta_w = (const float*)d_in[1];
    const float* g_w     = (const float*)d_in[2];
    const float* h_w     = (const float*)d_in[3];
    const float* h_b     = (const float*)d_in[4];
    float*       out     = (float*)d_out;

    init_kernel<<<1, 32>>>();

    dim3 grid1((N_ + 255) / 256, B_);
    reduce_kernel<<<grid1, 256>>>(x, theta_w, g_w);

    const int total_vec4 = B_ * CL_ * NV_;   // 6,422,528
    out_kernel<<<total_vec4 / 256, 256>>>(x, h_w, h_b, out);
}